// round 13
// baseline (speedup 1.0000x reference)
#include <cuda_runtime.h>
#include <cuda_bf16.h>
#include <cstdint>

// Problem constants
#define B_   2
#define S_   2048
#define D_   1024
#define NH_  16
#define HD_  64
#define M_   (B_*S_)   // 4096

// ---------------------------------------------------------------------------
// Scratch (bf16 hi/lo everywhere)
// ---------------------------------------------------------------------------
__device__ __nv_bfloat16 g_qh[(size_t)B_*NH_*S_*HD_];
__device__ __nv_bfloat16 g_ql[(size_t)B_*NH_*S_*HD_];
__device__ __nv_bfloat16 g_kh[(size_t)B_*NH_*S_*HD_];
__device__ __nv_bfloat16 g_kl[(size_t)B_*NH_*S_*HD_];
__device__ __nv_bfloat16 g_vh[(size_t)B_*NH_*S_*HD_];
__device__ __nv_bfloat16 g_vl[(size_t)B_*NH_*S_*HD_];
__device__ __nv_bfloat16 g_ctx_h[(size_t)M_*D_];
__device__ __nv_bfloat16 g_ctx_l[(size_t)M_*D_];
__device__ __nv_bfloat16 g_hid_h[(size_t)M_*D_];
__device__ __nv_bfloat16 g_hid_l[(size_t)M_*D_];
__device__ __nv_bfloat16 g_w_h[4][(size_t)D_*D_];
__device__ __nv_bfloat16 g_w_l[4][(size_t)D_*D_];

// ---------------------------------------------------------------------------
// helpers
// ---------------------------------------------------------------------------
__device__ __forceinline__ uint32_t cvta_smem(const void* p) {
    uint32_t a;
    asm("{ .reg .u64 t; cvta.to.shared.u64 t, %1; cvt.u32.u64 %0, t; }"
        : "=r"(a) : "l"(p));
    return a;
}
__device__ __forceinline__ void cp_async16(uint32_t s, const void* g) {
    asm volatile("cp.async.cg.shared.global [%0], [%1], 16;"
                 :: "r"(s), "l"(g) : "memory");
}
__device__ __forceinline__ void ldsm_x4(uint32_t (&r)[4], uint32_t addr) {
    asm volatile("ldmatrix.sync.aligned.m8n8.x4.shared.b16 {%0,%1,%2,%3}, [%4];"
                 : "=r"(r[0]), "=r"(r[1]), "=r"(r[2]), "=r"(r[3]) : "r"(addr));
}
__device__ __forceinline__ void ldsm_x4_t(uint32_t (&r)[4], uint32_t addr) {
    asm volatile("ldmatrix.sync.aligned.m8n8.x4.trans.shared.b16 {%0,%1,%2,%3}, [%4];"
                 : "=r"(r[0]), "=r"(r[1]), "=r"(r[2]), "=r"(r[3]) : "r"(addr));
}
__device__ __forceinline__ void mma_bf16(float (&c)[4], const uint32_t (&a)[4],
                                         uint32_t b0, uint32_t b1) {
    asm volatile("mma.sync.aligned.m16n8k16.row.col.f32.bf16.bf16.f32 "
                 "{%0,%1,%2,%3}, {%4,%5,%6,%7}, {%8,%9}, {%0,%1,%2,%3};"
                 : "+f"(c[0]), "+f"(c[1]), "+f"(c[2]), "+f"(c[3])
                 : "r"(a[0]), "r"(a[1]), "r"(a[2]), "r"(a[3]),
                   "r"(b0), "r"(b1));
}
__device__ __forceinline__ uint32_t pack_hl(float x, float y, uint32_t& lo) {
    __nv_bfloat162 h = __floats2bfloat162_rn(x, y);
    float rx = x - __bfloat162float(h.x);
    float ry = y - __bfloat162float(h.y);
    __nv_bfloat162 l = __floats2bfloat162_rn(rx, ry);
    lo = *reinterpret_cast<uint32_t*>(&l);
    return *reinterpret_cast<uint32_t*>(&h);
}

// ---------------------------------------------------------------------------
// fp32 -> bf16 hi/lo split
// ---------------------------------------------------------------------------
__global__ void __launch_bounds__(256)
split_kernel(const float* __restrict__ in, __nv_bfloat16* __restrict__ hi,
             __nv_bfloat16* __restrict__ lo, int n4)
{
    int i = blockIdx.x * blockDim.x + threadIdx.x;
    if (i >= n4) return;
    float4 v = ((const float4*)in)[i];
    uint32_t l0, l1;
    uint32_t h0 = pack_hl(v.x, v.y, l0);
    uint32_t h1 = pack_hl(v.z, v.w, l1);
    ((uint32_t*)hi)[2*i]   = h0;
    ((uint32_t*)hi)[2*i+1] = h1;
    ((uint32_t*)lo)[2*i]   = l0;
    ((uint32_t*)lo)[2*i+1] = l1;
}

// ---------------------------------------------------------------------------
// HMMA split-precision bf16 GEMM body (validated R6-R10)
// ---------------------------------------------------------------------------
#define KC      32
#define NKC     (D_/KC)
#define AST     40
#define ROWB    (AST*2)
#define TILE_B  (128*ROWB)
#define STAGE_B (4*TILE_B)
#define GSMEM   (2*STAGE_B)

__device__ __forceinline__ void gemm_body(
    const __nv_bfloat16* __restrict__ Ah, const __nv_bfloat16* __restrict__ Al,
    const __nv_bfloat16* __restrict__ Bh, const __nv_bfloat16* __restrict__ Bl,
    const float* __restrict__ bias, float* __restrict__ outp, int mode)
{
    extern __shared__ unsigned char smem_raw[];
    const uint32_t sbase = cvta_smem(smem_raw);

    const int tid  = threadIdx.x;
    const int wid  = tid >> 5;
    const int lane = tid & 31;
    const int wm   = wid & 3;
    const int wn   = wid >> 2;
    const int bm   = blockIdx.x * 128;
    const int bn   = blockIdx.y * 128;

    const __nv_bfloat16* srcs[4] = { Ah + (size_t)bm * D_, Al + (size_t)bm * D_,
                                     Bh + (size_t)bn * D_, Bl + (size_t)bn * D_ };

    float acc[2][8][4];
#pragma unroll
    for (int mt = 0; mt < 2; mt++)
#pragma unroll
        for (int nt = 0; nt < 8; nt++)
#pragma unroll
            for (int i = 0; i < 4; i++) acc[mt][nt][i] = 0.f;

#define LOAD_STAGE(kc, stg)                                                   \
    do {                                                                      \
        uint32_t sb_ = sbase + (stg) * STAGE_B;                               \
        int k0_ = (kc) * KC;                                                  \
        _Pragma("unroll")                                                     \
        for (int it = 0; it < 8; it++) {                                      \
            int idx  = tid + it * 256;                                        \
            int tile = idx >> 9;                                              \
            int rem  = idx & 511;                                             \
            int row  = rem >> 2;                                              \
            int q    = rem & 3;                                               \
            cp_async16(sb_ + tile * TILE_B + row * ROWB + q * 16,             \
                       srcs[tile] + (size_t)row * D_ + k0_ + q * 8);          \
        }                                                                     \
        asm volatile("cp.async.commit_group;" ::: "memory");                  \
    } while (0)

    LOAD_STAGE(0, 0);

    for (int kc = 0; kc < NKC; kc++) {
        if (kc + 1 < NKC) {
            LOAD_STAGE(kc + 1, (kc + 1) & 1);
            asm volatile("cp.async.wait_group 1;" ::: "memory");
        } else {
            asm volatile("cp.async.wait_group 0;" ::: "memory");
        }
        __syncthreads();

        const uint32_t st = sbase + (kc & 1) * STAGE_B;
        const uint32_t sAh = st + 0 * TILE_B;
        const uint32_t sAl = st + 1 * TILE_B;
        const uint32_t sBh = st + 2 * TILE_B;
        const uint32_t sBl = st + 3 * TILE_B;

#pragma unroll
        for (int ks = 0; ks < 2; ks++) {
            const int kofs = ks * 16;
            uint32_t ah[2][4], al[2][4];
            {
                int arow = wm * 32 + (lane & 15);
                int acol = ((lane >> 4) << 3) + kofs;
#pragma unroll
                for (int mt = 0; mt < 2; mt++) {
                    uint32_t off = (uint32_t)(arow + mt * 16) * ROWB + acol * 2;
                    ldsm_x4(ah[mt], sAh + off);
                    ldsm_x4(al[mt], sAl + off);
                }
            }
            uint32_t bh[8][2], bl[8][2];
            {
                int brow = wn * 64 + ((lane >> 4) << 3) + (lane & 7);
                int bcol = (((lane >> 3) & 1) << 3) + kofs;
#pragma unroll
                for (int p = 0; p < 4; p++) {
                    uint32_t off = (uint32_t)(brow + p * 16) * ROWB + bcol * 2;
                    uint32_t r[4];
                    ldsm_x4(r, sBh + off);
                    bh[2*p][0] = r[0]; bh[2*p][1] = r[1];
                    bh[2*p+1][0] = r[2]; bh[2*p+1][1] = r[3];
                    ldsm_x4(r, sBl + off);
                    bl[2*p][0] = r[0]; bl[2*p][1] = r[1];
                    bl[2*p+1][0] = r[2]; bl[2*p+1][1] = r[3];
                }
            }
#pragma unroll
            for (int mt = 0; mt < 2; mt++)
#pragma unroll
                for (int nt = 0; nt < 8; nt++) {
                    mma_bf16(acc[mt][nt], ah[mt], bh[nt][0], bh[nt][1]);
                    mma_bf16(acc[mt][nt], ah[mt], bl[nt][0], bl[nt][1]);
                    mma_bf16(acc[mt][nt], al[mt], bh[nt][0], bh[nt][1]);
                }
        }
        __syncthreads();
    }

    const int qr = lane >> 2;
    const int qc = (lane & 3) * 2;
    __nv_bfloat16* oh = (mode == 0) ? g_qh : (mode == 1) ? g_kh : g_vh;
    __nv_bfloat16* ol = (mode == 0) ? g_ql : (mode == 1) ? g_kl : g_vl;

#pragma unroll
    for (int mt = 0; mt < 2; mt++) {
#pragma unroll
        for (int half = 0; half < 2; half++) {
            int m = bm + wm * 32 + mt * 16 + qr + half * 8;
            int b = m >> 11;
            int s = m & (S_ - 1);
#pragma unroll
            for (int nt = 0; nt < 8; nt++) {
                int n = bn + wn * 64 + nt * 8 + qc;
                float ox = acc[mt][nt][2*half + 0] + bias[n + 0];
                float oy = acc[mt][nt][2*half + 1] + bias[n + 1];
                if (mode == 3) {
                    float2 o = make_float2(ox, oy);
                    *(float2*)&outp[(size_t)m * D_ + n] = o;
                } else {
                    int h  = n >> 6;
                    int hd = n & 63;
                    size_t off = ((size_t)((b*NH_ + h)*S_ + s))*HD_ + hd;
                    uint32_t lo;
                    uint32_t hi = pack_hl(ox, oy, lo);
                    *(uint32_t*)&oh[off] = hi;
                    *(uint32_t*)&ol[off] = lo;
                }
            }
        }
    }
}

// QKV fused: grid (32, 8, 3), z selects weight/bias/output
__global__ void __launch_bounds__(256)
gemm_qkv(const __nv_bfloat16* __restrict__ Ah, const __nv_bfloat16* __restrict__ Al,
         const __nv_bfloat16* __restrict__ Wh0, const __nv_bfloat16* __restrict__ Wl0,
         const float* __restrict__ bq, const float* __restrict__ bk,
         const float* __restrict__ bv)
{
    const int z = blockIdx.z;
    const float* bias = (z == 0) ? bq : (z == 1) ? bk : bv;
    gemm_body(Ah, Al, Wh0 + (size_t)z * D_ * D_, Wl0 + (size_t)z * D_ * D_,
              bias, nullptr, z);
}

__global__ void __launch_bounds__(256)
gemm_o(const __nv_bfloat16* __restrict__ Ah, const __nv_bfloat16* __restrict__ Al,
       const __nv_bfloat16* __restrict__ Bh, const __nv_bfloat16* __restrict__ Bl,
       const float* __restrict__ bias, float* __restrict__ outp)
{
    gemm_body(Ah, Al, Bh, Bl, bias, outp, 3);
}

// ---------------------------------------------------------------------------
// HMMA flash attention — EXACT R10 structure (epilogue-time at+mask add,
// 780.8us validated) + R13: L2 prefetch of next j's at-tile (2 prefetch
// instrs/thread, zero register-lifetime cost).
// ---------------------------------------------------------------------------
#define BQ      128
#define ATHREADS 128
#define BKV     64
#define AST2    72
#define ROW2B   (AST2*2)
#define QTILE_B (BQ*ROW2B)                // 18432
#define KVT_B   (BKV*ROW2B)               // 9216
#define KVSTG_B (4*KVT_B)                 // 36864
#define ASMEM   (2*QTILE_B + 2*KVSTG_B)   // 110592

__global__ void __launch_bounds__(ATHREADS)
attn_mma(const float* __restrict__ at, const float* __restrict__ mask,
         float* __restrict__ scores)
{
    extern __shared__ unsigned char smem_raw[];
    const uint32_t sbase = cvta_smem(smem_raw);

    const int tid  = threadIdx.x;
    const int wid  = tid >> 5;
    const int lane = tid & 31;
    const int bh   = blockIdx.y;
    const int b    = bh >> 4;
    const int h    = bh & 15;
    const int q0   = blockIdx.x * BQ;

    const __nv_bfloat16* qh = g_qh + (size_t)bh * S_ * HD_;
    const __nv_bfloat16* ql = g_ql + (size_t)bh * S_ * HD_;
    const __nv_bfloat16* kv_srcs[4] = {
        g_kh + (size_t)bh * S_ * HD_, g_kl + (size_t)bh * S_ * HD_,
        g_vh + (size_t)bh * S_ * HD_, g_vl + (size_t)bh * S_ * HD_ };

    // ---- load Q hi/lo (128 x 64) into smem ----
#pragma unroll
    for (int it = 0; it < 16; it++) {
        int idx  = tid + it * ATHREADS;      // 0..2047
        int half = idx >> 10;
        int rem  = idx & 1023;
        int row  = rem >> 3;
        int c    = rem & 7;
        const __nv_bfloat16* src = (half ? ql : qh) + (size_t)(q0 + row) * HD_ + c * 8;
        *(uint4*)(smem_raw + half * QTILE_B + row * ROW2B + c * 16) =
            *(const uint4*)src;
    }

    float cacc[2][8][4];
#pragma unroll
    for (int mt = 0; mt < 2; mt++)
#pragma unroll
        for (int nt = 0; nt < 8; nt++)
#pragma unroll
            for (int i = 0; i < 4; i++) cacc[mt][nt][i] = 0.f;
    float run_max[2][2], run_sum[2][2];
#pragma unroll
    for (int mt = 0; mt < 2; mt++) {
        run_max[mt][0] = -1e30f; run_max[mt][1] = -1e30f;
        run_sum[mt][0] = 0.f;    run_sum[mt][1] = 0.f;
    }

    const int qr  = lane >> 2;
    const int qc2 = (lane & 3) * 2;

#define KV_LOAD(jt, stg)                                                      \
    do {                                                                      \
        uint32_t sb_ = sbase + 2*QTILE_B + (stg) * KVSTG_B;                   \
        int r0_ = (jt) * BKV;                                                 \
        _Pragma("unroll")                                                     \
        for (int it = 0; it < 16; it++) {                                     \
            int idx  = tid + it * ATHREADS;                                   \
            int tile = idx >> 9;                                              \
            int rem  = idx & 511;                                             \
            int row  = rem >> 3;                                              \
            int c    = rem & 7;                                               \
            cp_async16(sb_ + tile * KVT_B + row * ROW2B + c * 16,             \
                       kv_srcs[tile] + (size_t)(r0_ + row) * HD_ + c * 8);    \
        }                                                                     \
        asm volatile("cp.async.commit_group;" ::: "memory");                  \
    } while (0)

    KV_LOAD(0, 0);

    const float scale = 0.125f;

    // L2-prefetch the j=0 at tile (covers the Q-load + first-wait window)
    {
        int row = tid >> 1, hf = tid & 1;
        const float* p = at + ((size_t)bh * S_ + (size_t)(q0 + row)) * S_ + hf * 32;
        asm volatile("prefetch.global.L2 [%0];" :: "l"(p));
        asm volatile("prefetch.global.L2 [%0];" :: "l"(p + (size_t)64 * S_));
    }

    for (int j = 0; j < S_/BKV; j++) {
        if (j + 1 < S_/BKV) {
            KV_LOAD(j + 1, (j + 1) & 1);
            // ---- R13: L2-prefetch next iteration's at tile.
            // 128 rows x 256B = 256 lines; 128 threads x 2 lines each.
            {
                int jn0 = (j + 1) * BKV;
                int row = tid >> 1, hf = tid & 1;
                const float* p = at + ((size_t)bh * S_ + (size_t)(q0 + row)) * S_
                               + jn0 + hf * 32;
                asm volatile("prefetch.global.L2 [%0];" :: "l"(p));
                asm volatile("prefetch.global.L2 [%0];" :: "l"(p + (size_t)64 * S_));
            }
            asm volatile("cp.async.wait_group 1;" ::: "memory");
        } else {
            asm volatile("cp.async.wait_group 0;" ::: "memory");
        }
        __syncthreads();

        const uint32_t st  = sbase + 2*QTILE_B + (j & 1) * KVSTG_B;
        const uint32_t sKh = st + 0 * KVT_B;
        const uint32_t sKl = st + 1 * KVT_B;
        const uint32_t sVh = st + 2 * KVT_B;
        const uint32_t sVl = st + 3 * KVT_B;

        // ---- S = Q @ K^T (3-pass), K frags shared across m-tiles ----
        float sacc[2][8][4];
#pragma unroll
        for (int mt = 0; mt < 2; mt++)
#pragma unroll
            for (int nt = 0; nt < 8; nt++)
#pragma unroll
                for (int i = 0; i < 4; i++) sacc[mt][nt][i] = 0.f;

#pragma unroll
        for (int ks = 0; ks < 4; ks++) {
            uint32_t qhf[2][4], qlf[2][4];
#pragma unroll
            for (int mt = 0; mt < 2; mt++) {
                uint32_t off = (uint32_t)(wid * 32 + mt * 16 + (lane & 15)) * ROW2B
                             + ks * 32 + ((lane >> 4) << 4);
                ldsm_x4(qhf[mt], sbase + off);
                ldsm_x4(qlf[mt], sbase + QTILE_B + off);
            }
#pragma unroll
            for (int np = 0; np < 4; np++) {
                int brow = np * 16 + ((lane >> 4) << 3) + (lane & 7);
                uint32_t off = (uint32_t)brow * ROW2B
                             + (((lane >> 3) & 1) << 4) + ks * 32;
                uint32_t rh[4], rl[4];
                ldsm_x4(rh, sKh + off);
                ldsm_x4(rl, sKl + off);
#pragma unroll
                for (int mt = 0; mt < 2; mt++) {
                    mma_bf16(sacc[mt][2*np],   qhf[mt], rh[0], rh[1]);
                    mma_bf16(sacc[mt][2*np],   qhf[mt], rl[0], rl[1]);
                    mma_bf16(sacc[mt][2*np],   qlf[mt], rh[0], rh[1]);
                    mma_bf16(sacc[mt][2*np+1], qhf[mt], rh[2], rh[3]);
                    mma_bf16(sacc[mt][2*np+1], qhf[mt], rl[2], rl[3]);
                    mma_bf16(sacc[mt][2*np+1], qlf[mt], rh[2], rh[3]);
                }
            }
        }

        // ---- epilogue per m-tile: scale + at + mask, scores, softmax ----
        const int j0 = j * BKV;
#pragma unroll
        for (int mt = 0; mt < 2; mt++) {
            const int row_l0 = wid * 32 + mt * 16 + qr;
            float rm0 = -1e30f, rm1 = -1e30f;
#pragma unroll
            for (int nt = 0; nt < 8; nt++) {
                int col = j0 + nt * 8 + qc2;
                float2 mk = *(const float2*)&mask[(size_t)b * S_ + col];
                size_t off0 = ((size_t)bh * S_ + (size_t)(q0 + row_l0)) * S_ + col;
                size_t off1 = off0 + (size_t)8 * S_;
                float2 a0 = *(const float2*)&at[off0];
                float2 a1 = *(const float2*)&at[off1];
                sacc[mt][nt][0] = fmaf(sacc[mt][nt][0], scale, a0.x) + mk.x;
                sacc[mt][nt][1] = fmaf(sacc[mt][nt][1], scale, a0.y) + mk.y;
                sacc[mt][nt][2] = fmaf(sacc[mt][nt][2], scale, a1.x) + mk.x;
                sacc[mt][nt][3] = fmaf(sacc[mt][nt][3], scale, a1.y) + mk.y;
                *(float2*)&scores[off0] = make_float2(sacc[mt][nt][0], sacc[mt][nt][1]);
                *(float2*)&scores[off1] = make_float2(sacc[mt][nt][2], sacc[mt][nt][3]);
                rm0 = fmaxf(rm0, fmaxf(sacc[mt][nt][0], sacc[mt][nt][1]));
                rm1 = fmaxf(rm1, fmaxf(sacc[mt][nt][2], sacc[mt][nt][3]));
            }
            rm0 = fmaxf(rm0, __shfl_xor_sync(0xffffffffu, rm0, 1));
            rm0 = fmaxf(rm0, __shfl_xor_sync(0xffffffffu, rm0, 2));
            rm1 = fmaxf(rm1, __shfl_xor_sync(0xffffffffu, rm1, 1));
            rm1 = fmaxf(rm1, __shfl_xor_sync(0xffffffffu, rm1, 2));

            float nm0 = fmaxf(run_max[mt][0], rm0);
            float nm1 = fmaxf(run_max[mt][1], rm1);
            float alpha0 = __expf(run_max[mt][0] - nm0);
            float alpha1 = __expf(run_max[mt][1] - nm1);
            run_max[mt][0] = nm0; run_max[mt][1] = nm1;

            float ps0 = 0.f, ps1 = 0.f;
#pragma unroll
            for (int nt = 0; nt < 8; nt++) {
                sacc[mt][nt][0] = __expf(sacc[mt][nt][0] - nm0);
                sacc[mt][nt][1] = __expf(sacc[mt][nt][1] - nm0);
                sacc[mt][nt][2] = __expf(sacc[mt][nt][2] - nm1);
                sacc[mt][nt][3] = __expf(sacc[mt][nt][3] - nm1);
                ps0 += sacc[mt][nt][0] + sacc[mt][nt][1];
                ps1 += sacc[mt][nt][2] + sacc[mt][nt][3];
            }
            ps0 += __shfl_xor_sync(0xffffffffu, ps0, 1);
            ps0 += __shfl_xor_sync(0xffffffffu, ps0, 2);
            ps1 += __shfl_xor_sync(0xffffffffu, ps1, 1);
            ps1 += __shfl_xor_sync(0xffffffffu, ps1, 2);
            run_sum[mt][0] = run_sum[mt][0] * alpha0 + ps0;
            run_sum[mt][1] = run_sum[mt][1] * alpha1 + ps1;

#pragma unroll
            for (int nt = 0; nt < 8; nt++) {
                cacc[mt][nt][0] *= alpha0; cacc[mt][nt][1] *= alpha0;
                cacc[mt][nt][2] *= alpha1; cacc[mt][nt][3] *= alpha1;
            }
        }

        // ---- ctx += P @ V (3-pass); V frags shared across m-tiles ----
#pragma unroll
        for (int kk = 0; kk < 4; kk++) {
            uint32_t pah[2][4], pal[2][4];
#pragma unroll
            for (int mt = 0; mt < 2; mt++) {
                pah[mt][0] = pack_hl(sacc[mt][2*kk][0],   sacc[mt][2*kk][1],   pal[mt][0]);
                pah[mt][1] = pack_hl(sacc[mt][2*kk][2],   sacc[mt][2*kk][3],   pal[mt][1]);
                pah[mt][2] = pack_hl(sacc[mt][2*kk+1][0], sacc[mt][2*kk+1][1], pal[mt][2]);
                pah[mt][3] = pack_hl(sacc[mt][2*kk+1][2], sacc[mt][2*kk+1][3], pal[mt][3]);
            }
#pragma unroll
            for (int np = 0; np < 4; np++) {
                uint32_t off = (uint32_t)(kk * 16 + (lane & 15)) * ROW2B
                             + np * 32 + ((lane >> 4) << 4);
                uint32_t vh[4], vl[4];
                ldsm_x4_t(vh, sVh + off);
                ldsm_x4_t(vl, sVl + off);
#pragma unroll
                for (int mt = 0; mt < 2; mt++) {
                    mma_bf16(cacc[mt][2*np],   pah[mt], vh[0], vh[1]);
                    mma_bf16(cacc[mt][2*np],   pal[mt], vh[0], vh[1]);
                    mma_bf16(cacc[mt][2*np],   pah[mt], vl[0], vl[1]);
                    mma_bf16(cacc[mt][2*np+1], pah[mt], vh[2], vh[3]);
                    mma_bf16(cacc[mt][2*np+1], pal[mt], vh[2], vh[3]);
                    mma_bf16(cacc[mt][2*np+1], pah[mt], vl[2], vl[3]);
                }
            }
        }
        __syncthreads();
    }

    // ---- final: ctx hi/lo -> g_ctx_h/l [B,S,D] ----
#pragma unroll
    for (int mt = 0; mt < 2; mt++) {
        float inv0 = 1.f / run_sum[mt][0];
        float inv1 = 1.f / run_sum[mt][1];
        size_t grow0 = (size_t)b * S_ + (q0 + wid * 32 + mt * 16 + qr);
#pragma unroll
        for (int nt = 0; nt < 8; nt++) {
            int col = h * HD_ + nt * 8 + qc2;
            uint32_t lo;
            uint32_t hi = pack_hl(cacc[mt][nt][0] * inv0, cacc[mt][nt][1] * inv0, lo);
            *(uint32_t*)&g_ctx_h[grow0 * D_ + col] = hi;
            *(uint32_t*)&g_ctx_l[grow0 * D_ + col] = lo;
            hi = pack_hl(cacc[mt][nt][2] * inv1, cacc[mt][nt][3] * inv1, lo);
            *(uint32_t*)&g_ctx_h[(grow0 + 8) * D_ + col] = hi;
            *(uint32_t*)&g_ctx_l[(grow0 + 8) * D_ + col] = lo;
        }
    }
}

// ---------------------------------------------------------------------------
extern "C" void kernel_launch(void* const* d_in, const int* in_sizes, int n_in,
                              void* d_out, int out_size)
{
    const float* hidden = (const float*)d_in[0];
    const float* mask   = (const float*)d_in[1];
    const float* at     = (const float*)d_in[2];
    const float* Wq     = (const float*)d_in[3];
    const float* bq     = (const float*)d_in[4];
    const float* Wk     = (const float*)d_in[5];
    const float* bk     = (const float*)d_in[6];
    const float* Wv     = (const float*)d_in[7];
    const float* bv     = (const float*)d_in[8];
    const float* Wo     = (const float*)d_in[9];
    const float* bo     = (const float*)d_in[10];

    float* outp = (float*)d_out;
    const int OUT_ELEMS = 4194304;            // B*S*D
    float* scores = (out_size >= OUT_ELEMS + 1) ? (outp + OUT_ELEMS) : nullptr;

    cudaFuncSetAttribute(gemm_qkv, cudaFuncAttributeMaxDynamicSharedMemorySize,
                         GSMEM);
    cudaFuncSetAttribute(gemm_o, cudaFuncAttributeMaxDynamicSharedMemorySize,
                         GSMEM);
    cudaFuncSetAttribute(attn_mma, cudaFuncAttributeMaxDynamicSharedMemorySize,
                         ASMEM);

    __nv_bfloat16 *hid_h, *hid_l, *ctx_h, *ctx_l, *w_h0, *w_l0;
    cudaGetSymbolAddress((void**)&hid_h, g_hid_h);
    cudaGetSymbolAddress((void**)&hid_l, g_hid_l);
    cudaGetSymbolAddress((void**)&ctx_h, g_ctx_h);
    cudaGetSymbolAddress((void**)&ctx_l, g_ctx_l);
    cudaGetSymbolAddress((void**)&w_h0, g_w_h);
    cudaGetSymbolAddress((void**)&w_l0, g_w_l);

    // 1) split fp32 -> bf16 hi/lo
    const int n4_hid = M_ * D_ / 4;
    const int n4_w   = D_ * D_ / 4;
    split_kernel<<<(n4_hid + 255)/256, 256>>>(hidden, hid_h, hid_l, n4_hid);
    split_kernel<<<(n4_w + 255)/256, 256>>>(Wq, w_h0 + 0*(size_t)D_*D_, w_l0 + 0*(size_t)D_*D_, n4_w);
    split_kernel<<<(n4_w + 255)/256, 256>>>(Wk, w_h0 + 1*(size_t)D_*D_, w_l0 + 1*(size_t)D_*D_, n4_w);
    split_kernel<<<(n4_w + 255)/256, 256>>>(Wv, w_h0 + 2*(size_t)D_*D_, w_l0 + 2*(size_t)D_*D_, n4_w);
    split_kernel<<<(n4_w + 255)/256, 256>>>(Wo, w_h0 + 3*(size_t)D_*D_, w_l0 + 3*(size_t)D_*D_, n4_w);

    // 2) QKV projections — ONE launch, grid.z = 3
    dim3 gq(M_/128, D_/128, 3);
    gemm_qkv<<<gq, 256, GSMEM>>>(hid_h, hid_l, w_h0, w_l0, bq, bk, bv);

    // 3) attention (HMMA flash, R10 epilogue + at L2-prefetch)
    dim3 ga(S_/BQ, B_*NH_);              // 16 x 32
    attn_mma<<<ga, ATHREADS, ASMEM>>>(at, mask, scores);

    // 4) O projection
    dim3 gg(M_/128, D_/128);
    gemm_o<<<gg, 256, GSMEM>>>(ctx_h, ctx_l,
                               w_h0 + 3*(size_t)D_*D_, w_l0 + 3*(size_t)D_*D_,
                               bo, outp);
}

// round 14
// speedup vs baseline: 1.2068x; 1.2068x over previous
#include <cuda_runtime.h>
#include <cuda_bf16.h>
#include <cstdint>

// Problem constants
#define B_   2
#define S_   2048
#define D_   1024
#define NH_  16
#define HD_  64
#define M_   (B_*S_)   // 4096

// ---------------------------------------------------------------------------
// Scratch (bf16 hi/lo everywhere)
// ---------------------------------------------------------------------------
__device__ __nv_bfloat16 g_qh[(size_t)B_*NH_*S_*HD_];
__device__ __nv_bfloat16 g_ql[(size_t)B_*NH_*S_*HD_];
__device__ __nv_bfloat16 g_kh[(size_t)B_*NH_*S_*HD_];
__device__ __nv_bfloat16 g_kl[(size_t)B_*NH_*S_*HD_];
__device__ __nv_bfloat16 g_vh[(size_t)B_*NH_*S_*HD_];
__device__ __nv_bfloat16 g_vl[(size_t)B_*NH_*S_*HD_];
__device__ __nv_bfloat16 g_ctx_h[(size_t)M_*D_];
__device__ __nv_bfloat16 g_ctx_l[(size_t)M_*D_];
__device__ __nv_bfloat16 g_hid_h[(size_t)M_*D_];
__device__ __nv_bfloat16 g_hid_l[(size_t)M_*D_];
__device__ __nv_bfloat16 g_w_h[4][(size_t)D_*D_];
__device__ __nv_bfloat16 g_w_l[4][(size_t)D_*D_];

// ---------------------------------------------------------------------------
// helpers
// ---------------------------------------------------------------------------
__device__ __forceinline__ uint32_t cvta_smem(const void* p) {
    uint32_t a;
    asm("{ .reg .u64 t; cvta.to.shared.u64 t, %1; cvt.u32.u64 %0, t; }"
        : "=r"(a) : "l"(p));
    return a;
}
__device__ __forceinline__ void cp_async16(uint32_t s, const void* g) {
    asm volatile("cp.async.cg.shared.global [%0], [%1], 16;"
                 :: "r"(s), "l"(g) : "memory");
}
__device__ __forceinline__ void ldsm_x4(uint32_t (&r)[4], uint32_t addr) {
    asm volatile("ldmatrix.sync.aligned.m8n8.x4.shared.b16 {%0,%1,%2,%3}, [%4];"
                 : "=r"(r[0]), "=r"(r[1]), "=r"(r[2]), "=r"(r[3]) : "r"(addr));
}
__device__ __forceinline__ void ldsm_x4_t(uint32_t (&r)[4], uint32_t addr) {
    asm volatile("ldmatrix.sync.aligned.m8n8.x4.trans.shared.b16 {%0,%1,%2,%3}, [%4];"
                 : "=r"(r[0]), "=r"(r[1]), "=r"(r[2]), "=r"(r[3]) : "r"(addr));
}
__device__ __forceinline__ void mma_bf16(float (&c)[4], const uint32_t (&a)[4],
                                         uint32_t b0, uint32_t b1) {
    asm volatile("mma.sync.aligned.m16n8k16.row.col.f32.bf16.bf16.f32 "
                 "{%0,%1,%2,%3}, {%4,%5,%6,%7}, {%8,%9}, {%0,%1,%2,%3};"
                 : "+f"(c[0]), "+f"(c[1]), "+f"(c[2]), "+f"(c[3])
                 : "r"(a[0]), "r"(a[1]), "r"(a[2]), "r"(a[3]),
                   "r"(b0), "r"(b1));
}
__device__ __forceinline__ uint32_t pack_hl(float x, float y, uint32_t& lo) {
    __nv_bfloat162 h = __floats2bfloat162_rn(x, y);
    float rx = x - __bfloat162float(h.x);
    float ry = y - __bfloat162float(h.y);
    __nv_bfloat162 l = __floats2bfloat162_rn(rx, ry);
    lo = *reinterpret_cast<uint32_t*>(&l);
    return *reinterpret_cast<uint32_t*>(&h);
}

// ---------------------------------------------------------------------------
// fp32 -> bf16 hi/lo split (single tensor)
// ---------------------------------------------------------------------------
__global__ void __launch_bounds__(256)
split_kernel(const float* __restrict__ in, __nv_bfloat16* __restrict__ hi,
             __nv_bfloat16* __restrict__ lo, int n4)
{
    int i = blockIdx.x * blockDim.x + threadIdx.x;
    if (i >= n4) return;
    float4 v = ((const float4*)in)[i];
    uint32_t l0, l1;
    uint32_t h0 = pack_hl(v.x, v.y, l0);
    uint32_t h1 = pack_hl(v.z, v.w, l1);
    ((uint32_t*)hi)[2*i]   = h0;
    ((uint32_t*)hi)[2*i+1] = h1;
    ((uint32_t*)lo)[2*i]   = l0;
    ((uint32_t*)lo)[2*i+1] = l1;
}

// R14: batched weight split — 4 weight matrices in one launch (grid.y picks
// source; destinations are contiguous in g_w_h/g_w_l). Isolated change.
__global__ void __launch_bounds__(256)
split4_kernel(const float* __restrict__ w0, const float* __restrict__ w1,
              const float* __restrict__ w2, const float* __restrict__ w3,
              __nv_bfloat16* __restrict__ hi, __nv_bfloat16* __restrict__ lo,
              int n4)
{
    int i = blockIdx.x * blockDim.x + threadIdx.x;
    if (i >= n4) return;
    int z = blockIdx.y;
    const float* in = (z == 0) ? w0 : (z == 1) ? w1 : (z == 2) ? w2 : w3;
    size_t base = (size_t)z * n4;
    float4 v = ((const float4*)in)[i];
    uint32_t l0, l1;
    uint32_t h0 = pack_hl(v.x, v.y, l0);
    uint32_t h1 = pack_hl(v.z, v.w, l1);
    ((uint32_t*)hi)[2*(base + i)]   = h0;
    ((uint32_t*)hi)[2*(base + i)+1] = h1;
    ((uint32_t*)lo)[2*(base + i)]   = l0;
    ((uint32_t*)lo)[2*(base + i)+1] = l1;
}

// ---------------------------------------------------------------------------
// HMMA split-precision bf16 GEMM (EXACT R10 monolithic kernel)
// ---------------------------------------------------------------------------
#define KC      32
#define NKC     (D_/KC)
#define AST     40
#define ROWB    (AST*2)
#define TILE_B  (128*ROWB)
#define STAGE_B (4*TILE_B)
#define GSMEM   (2*STAGE_B)

__global__ void __launch_bounds__(256)
gemm_mma(const __nv_bfloat16* __restrict__ Ah, const __nv_bfloat16* __restrict__ Al,
         const __nv_bfloat16* __restrict__ Bh, const __nv_bfloat16* __restrict__ Bl,
         const float* __restrict__ bias, float* __restrict__ outp, int mode)
{
    extern __shared__ unsigned char smem_raw[];
    const uint32_t sbase = cvta_smem(smem_raw);

    const int tid  = threadIdx.x;
    const int wid  = tid >> 5;
    const int lane = tid & 31;
    const int wm   = wid & 3;
    const int wn   = wid >> 2;
    const int bm   = blockIdx.x * 128;
    const int bn   = blockIdx.y * 128;

    const __nv_bfloat16* srcs[4] = { Ah + (size_t)bm * D_, Al + (size_t)bm * D_,
                                     Bh + (size_t)bn * D_, Bl + (size_t)bn * D_ };

    float acc[2][8][4];
#pragma unroll
    for (int mt = 0; mt < 2; mt++)
#pragma unroll
        for (int nt = 0; nt < 8; nt++)
#pragma unroll
            for (int i = 0; i < 4; i++) acc[mt][nt][i] = 0.f;

#define LOAD_STAGE(kc, stg)                                                   \
    do {                                                                      \
        uint32_t sb_ = sbase + (stg) * STAGE_B;                               \
        int k0_ = (kc) * KC;                                                  \
        _Pragma("unroll")                                                     \
        for (int it = 0; it < 8; it++) {                                      \
            int idx  = tid + it * 256;                                        \
            int tile = idx >> 9;                                              \
            int rem  = idx & 511;                                             \
            int row  = rem >> 2;                                              \
            int q    = rem & 3;                                               \
            cp_async16(sb_ + tile * TILE_B + row * ROWB + q * 16,             \
                       srcs[tile] + (size_t)row * D_ + k0_ + q * 8);          \
        }                                                                     \
        asm volatile("cp.async.commit_group;" ::: "memory");                  \
    } while (0)

    LOAD_STAGE(0, 0);

    for (int kc = 0; kc < NKC; kc++) {
        if (kc + 1 < NKC) {
            LOAD_STAGE(kc + 1, (kc + 1) & 1);
            asm volatile("cp.async.wait_group 1;" ::: "memory");
        } else {
            asm volatile("cp.async.wait_group 0;" ::: "memory");
        }
        __syncthreads();

        const uint32_t st = sbase + (kc & 1) * STAGE_B;
        const uint32_t sAh = st + 0 * TILE_B;
        const uint32_t sAl = st + 1 * TILE_B;
        const uint32_t sBh = st + 2 * TILE_B;
        const uint32_t sBl = st + 3 * TILE_B;

#pragma unroll
        for (int ks = 0; ks < 2; ks++) {
            const int kofs = ks * 16;
            uint32_t ah[2][4], al[2][4];
            {
                int arow = wm * 32 + (lane & 15);
                int acol = ((lane >> 4) << 3) + kofs;
#pragma unroll
                for (int mt = 0; mt < 2; mt++) {
                    uint32_t off = (uint32_t)(arow + mt * 16) * ROWB + acol * 2;
                    ldsm_x4(ah[mt], sAh + off);
                    ldsm_x4(al[mt], sAl + off);
                }
            }
            uint32_t bh[8][2], bl[8][2];
            {
                int brow = wn * 64 + ((lane >> 4) << 3) + (lane & 7);
                int bcol = (((lane >> 3) & 1) << 3) + kofs;
#pragma unroll
                for (int p = 0; p < 4; p++) {
                    uint32_t off = (uint32_t)(brow + p * 16) * ROWB + bcol * 2;
                    uint32_t r[4];
                    ldsm_x4(r, sBh + off);
                    bh[2*p][0] = r[0]; bh[2*p][1] = r[1];
                    bh[2*p+1][0] = r[2]; bh[2*p+1][1] = r[3];
                    ldsm_x4(r, sBl + off);
                    bl[2*p][0] = r[0]; bl[2*p][1] = r[1];
                    bl[2*p+1][0] = r[2]; bl[2*p+1][1] = r[3];
                }
            }
#pragma unroll
            for (int mt = 0; mt < 2; mt++)
#pragma unroll
                for (int nt = 0; nt < 8; nt++) {
                    mma_bf16(acc[mt][nt], ah[mt], bh[nt][0], bh[nt][1]);
                    mma_bf16(acc[mt][nt], ah[mt], bl[nt][0], bl[nt][1]);
                    mma_bf16(acc[mt][nt], al[mt], bh[nt][0], bh[nt][1]);
                }
        }
        __syncthreads();
    }

    const int qr = lane >> 2;
    const int qc = (lane & 3) * 2;
    __nv_bfloat16* oh = (mode == 0) ? g_qh : (mode == 1) ? g_kh : g_vh;
    __nv_bfloat16* ol = (mode == 0) ? g_ql : (mode == 1) ? g_kl : g_vl;

#pragma unroll
    for (int mt = 0; mt < 2; mt++) {
#pragma unroll
        for (int half = 0; half < 2; half++) {
            int m = bm + wm * 32 + mt * 16 + qr + half * 8;
            int b = m >> 11;
            int s = m & (S_ - 1);
#pragma unroll
            for (int nt = 0; nt < 8; nt++) {
                int n = bn + wn * 64 + nt * 8 + qc;
                float ox = acc[mt][nt][2*half + 0] + bias[n + 0];
                float oy = acc[mt][nt][2*half + 1] + bias[n + 1];
                if (mode == 3) {
                    float2 o = make_float2(ox, oy);
                    *(float2*)&outp[(size_t)m * D_ + n] = o;
                } else {
                    int h  = n >> 6;
                    int hd = n & 63;
                    size_t off = ((size_t)((b*NH_ + h)*S_ + s))*HD_ + hd;
                    uint32_t lo;
                    uint32_t hi = pack_hl(ox, oy, lo);
                    *(uint32_t*)&oh[off] = hi;
                    *(uint32_t*)&ol[off] = lo;
                }
            }
        }
    }
}

// ---------------------------------------------------------------------------
// HMMA flash attention — EXACT R10 (780.8us validated): BQ=128, 4 warps x
// 32 rows, epilogue-time at+mask, no prefetch, no preload.
// ---------------------------------------------------------------------------
#define BQ      128
#define ATHREADS 128
#define BKV     64
#define AST2    72
#define ROW2B   (AST2*2)
#define QTILE_B (BQ*ROW2B)                // 18432
#define KVT_B   (BKV*ROW2B)               // 9216
#define KVSTG_B (4*KVT_B)                 // 36864
#define ASMEM   (2*QTILE_B + 2*KVSTG_B)   // 110592

__global__ void __launch_bounds__(ATHREADS)
attn_mma(const float* __restrict__ at, const float* __restrict__ mask,
         float* __restrict__ scores)
{
    extern __shared__ unsigned char smem_raw[];
    const uint32_t sbase = cvta_smem(smem_raw);

    const int tid  = threadIdx.x;
    const int wid  = tid >> 5;
    const int lane = tid & 31;
    const int bh   = blockIdx.y;
    const int b    = bh >> 4;
    const int h    = bh & 15;
    const int q0   = blockIdx.x * BQ;

    const __nv_bfloat16* qh = g_qh + (size_t)bh * S_ * HD_;
    const __nv_bfloat16* ql = g_ql + (size_t)bh * S_ * HD_;
    const __nv_bfloat16* kv_srcs[4] = {
        g_kh + (size_t)bh * S_ * HD_, g_kl + (size_t)bh * S_ * HD_,
        g_vh + (size_t)bh * S_ * HD_, g_vl + (size_t)bh * S_ * HD_ };

    // ---- load Q hi/lo (128 x 64) into smem ----
#pragma unroll
    for (int it = 0; it < 16; it++) {
        int idx  = tid + it * ATHREADS;      // 0..2047
        int half = idx >> 10;
        int rem  = idx & 1023;
        int row  = rem >> 3;
        int c    = rem & 7;
        const __nv_bfloat16* src = (half ? ql : qh) + (size_t)(q0 + row) * HD_ + c * 8;
        *(uint4*)(smem_raw + half * QTILE_B + row * ROW2B + c * 16) =
            *(const uint4*)src;
    }

    float cacc[2][8][4];
#pragma unroll
    for (int mt = 0; mt < 2; mt++)
#pragma unroll
        for (int nt = 0; nt < 8; nt++)
#pragma unroll
            for (int i = 0; i < 4; i++) cacc[mt][nt][i] = 0.f;
    float run_max[2][2], run_sum[2][2];
#pragma unroll
    for (int mt = 0; mt < 2; mt++) {
        run_max[mt][0] = -1e30f; run_max[mt][1] = -1e30f;
        run_sum[mt][0] = 0.f;    run_sum[mt][1] = 0.f;
    }

    const int qr  = lane >> 2;
    const int qc2 = (lane & 3) * 2;

#define KV_LOAD(jt, stg)                                                      \
    do {                                                                      \
        uint32_t sb_ = sbase + 2*QTILE_B + (stg) * KVSTG_B;                   \
        int r0_ = (jt) * BKV;                                                 \
        _Pragma("unroll")                                                     \
        for (int it = 0; it < 16; it++) {                                     \
            int idx  = tid + it * ATHREADS;                                   \
            int tile = idx >> 9;                                              \
            int rem  = idx & 511;                                             \
            int row  = rem >> 3;                                              \
            int c    = rem & 7;                                               \
            cp_async16(sb_ + tile * KVT_B + row * ROW2B + c * 16,             \
                       kv_srcs[tile] + (size_t)(r0_ + row) * HD_ + c * 8);    \
        }                                                                     \
        asm volatile("cp.async.commit_group;" ::: "memory");                  \
    } while (0)

    KV_LOAD(0, 0);

    const float scale = 0.125f;

    for (int j = 0; j < S_/BKV; j++) {
        if (j + 1 < S_/BKV) {
            KV_LOAD(j + 1, (j + 1) & 1);
            asm volatile("cp.async.wait_group 1;" ::: "memory");
        } else {
            asm volatile("cp.async.wait_group 0;" ::: "memory");
        }
        __syncthreads();

        const uint32_t st  = sbase + 2*QTILE_B + (j & 1) * KVSTG_B;
        const uint32_t sKh = st + 0 * KVT_B;
        const uint32_t sKl = st + 1 * KVT_B;
        const uint32_t sVh = st + 2 * KVT_B;
        const uint32_t sVl = st + 3 * KVT_B;

        // ---- S = Q @ K^T (3-pass), K frags shared across m-tiles ----
        float sacc[2][8][4];
#pragma unroll
        for (int mt = 0; mt < 2; mt++)
#pragma unroll
            for (int nt = 0; nt < 8; nt++)
#pragma unroll
                for (int i = 0; i < 4; i++) sacc[mt][nt][i] = 0.f;

#pragma unroll
        for (int ks = 0; ks < 4; ks++) {
            uint32_t qhf[2][4], qlf[2][4];
#pragma unroll
            for (int mt = 0; mt < 2; mt++) {
                uint32_t off = (uint32_t)(wid * 32 + mt * 16 + (lane & 15)) * ROW2B
                             + ks * 32 + ((lane >> 4) << 4);
                ldsm_x4(qhf[mt], sbase + off);
                ldsm_x4(qlf[mt], sbase + QTILE_B + off);
            }
#pragma unroll
            for (int np = 0; np < 4; np++) {
                int brow = np * 16 + ((lane >> 4) << 3) + (lane & 7);
                uint32_t off = (uint32_t)brow * ROW2B
                             + (((lane >> 3) & 1) << 4) + ks * 32;
                uint32_t rh[4], rl[4];
                ldsm_x4(rh, sKh + off);
                ldsm_x4(rl, sKl + off);
#pragma unroll
                for (int mt = 0; mt < 2; mt++) {
                    mma_bf16(sacc[mt][2*np],   qhf[mt], rh[0], rh[1]);
                    mma_bf16(sacc[mt][2*np],   qhf[mt], rl[0], rl[1]);
                    mma_bf16(sacc[mt][2*np],   qlf[mt], rh[0], rh[1]);
                    mma_bf16(sacc[mt][2*np+1], qhf[mt], rh[2], rh[3]);
                    mma_bf16(sacc[mt][2*np+1], qhf[mt], rl[2], rl[3]);
                    mma_bf16(sacc[mt][2*np+1], qlf[mt], rh[2], rh[3]);
                }
            }
        }

        // ---- epilogue per m-tile: scale + at + mask, scores, softmax ----
        const int j0 = j * BKV;
#pragma unroll
        for (int mt = 0; mt < 2; mt++) {
            const int row_l0 = wid * 32 + mt * 16 + qr;
            float rm0 = -1e30f, rm1 = -1e30f;
#pragma unroll
            for (int nt = 0; nt < 8; nt++) {
                int col = j0 + nt * 8 + qc2;
                float2 mk = *(const float2*)&mask[(size_t)b * S_ + col];
                size_t off0 = ((size_t)bh * S_ + (size_t)(q0 + row_l0)) * S_ + col;
                size_t off1 = off0 + (size_t)8 * S_;
                float2 a0 = *(const float2*)&at[off0];
                float2 a1 = *(const float2*)&at[off1];
                sacc[mt][nt][0] = fmaf(sacc[mt][nt][0], scale, a0.x) + mk.x;
                sacc[mt][nt][1] = fmaf(sacc[mt][nt][1], scale, a0.y) + mk.y;
                sacc[mt][nt][2] = fmaf(sacc[mt][nt][2], scale, a1.x) + mk.x;
                sacc[mt][nt][3] = fmaf(sacc[mt][nt][3], scale, a1.y) + mk.y;
                *(float2*)&scores[off0] = make_float2(sacc[mt][nt][0], sacc[mt][nt][1]);
                *(float2*)&scores[off1] = make_float2(sacc[mt][nt][2], sacc[mt][nt][3]);
                rm0 = fmaxf(rm0, fmaxf(sacc[mt][nt][0], sacc[mt][nt][1]));
                rm1 = fmaxf(rm1, fmaxf(sacc[mt][nt][2], sacc[mt][nt][3]));
            }
            rm0 = fmaxf(rm0, __shfl_xor_sync(0xffffffffu, rm0, 1));
            rm0 = fmaxf(rm0, __shfl_xor_sync(0xffffffffu, rm0, 2));
            rm1 = fmaxf(rm1, __shfl_xor_sync(0xffffffffu, rm1, 1));
            rm1 = fmaxf(rm1, __shfl_xor_sync(0xffffffffu, rm1, 2));

            float nm0 = fmaxf(run_max[mt][0], rm0);
            float nm1 = fmaxf(run_max[mt][1], rm1);
            float alpha0 = __expf(run_max[mt][0] - nm0);
            float alpha1 = __expf(run_max[mt][1] - nm1);
            run_max[mt][0] = nm0; run_max[mt][1] = nm1;

            float ps0 = 0.f, ps1 = 0.f;
#pragma unroll
            for (int nt = 0; nt < 8; nt++) {
                sacc[mt][nt][0] = __expf(sacc[mt][nt][0] - nm0);
                sacc[mt][nt][1] = __expf(sacc[mt][nt][1] - nm0);
                sacc[mt][nt][2] = __expf(sacc[mt][nt][2] - nm1);
                sacc[mt][nt][3] = __expf(sacc[mt][nt][3] - nm1);
                ps0 += sacc[mt][nt][0] + sacc[mt][nt][1];
                ps1 += sacc[mt][nt][2] + sacc[mt][nt][3];
            }
            ps0 += __shfl_xor_sync(0xffffffffu, ps0, 1);
            ps0 += __shfl_xor_sync(0xffffffffu, ps0, 2);
            ps1 += __shfl_xor_sync(0xffffffffu, ps1, 1);
            ps1 += __shfl_xor_sync(0xffffffffu, ps1, 2);
            run_sum[mt][0] = run_sum[mt][0] * alpha0 + ps0;
            run_sum[mt][1] = run_sum[mt][1] * alpha1 + ps1;

#pragma unroll
            for (int nt = 0; nt < 8; nt++) {
                cacc[mt][nt][0] *= alpha0; cacc[mt][nt][1] *= alpha0;
                cacc[mt][nt][2] *= alpha1; cacc[mt][nt][3] *= alpha1;
            }
        }

        // ---- ctx += P @ V (3-pass); V frags shared across m-tiles ----
#pragma unroll
        for (int kk = 0; kk < 4; kk++) {
            uint32_t pah[2][4], pal[2][4];
#pragma unroll
            for (int mt = 0; mt < 2; mt++) {
                pah[mt][0] = pack_hl(sacc[mt][2*kk][0],   sacc[mt][2*kk][1],   pal[mt][0]);
                pah[mt][1] = pack_hl(sacc[mt][2*kk][2],   sacc[mt][2*kk][3],   pal[mt][1]);
                pah[mt][2] = pack_hl(sacc[mt][2*kk+1][0], sacc[mt][2*kk+1][1], pal[mt][2]);
                pah[mt][3] = pack_hl(sacc[mt][2*kk+1][2], sacc[mt][2*kk+1][3], pal[mt][3]);
            }
#pragma unroll
            for (int np = 0; np < 4; np++) {
                uint32_t off = (uint32_t)(kk * 16 + (lane & 15)) * ROW2B
                             + np * 32 + ((lane >> 4) << 4);
                uint32_t vh[4], vl[4];
                ldsm_x4_t(vh, sVh + off);
                ldsm_x4_t(vl, sVl + off);
#pragma unroll
                for (int mt = 0; mt < 2; mt++) {
                    mma_bf16(cacc[mt][2*np],   pah[mt], vh[0], vh[1]);
                    mma_bf16(cacc[mt][2*np],   pal[mt], vh[0], vh[1]);
                    mma_bf16(cacc[mt][2*np],   pah[mt], vl[0], vl[1]);
                    mma_bf16(cacc[mt][2*np+1], pah[mt], vh[2], vh[3]);
                    mma_bf16(cacc[mt][2*np+1], pal[mt], vh[2], vh[3]);
                    mma_bf16(cacc[mt][2*np+1], pah[mt], vl[2], vl[3]);
                }
            }
        }
        __syncthreads();
    }

    // ---- final: ctx hi/lo -> g_ctx_h/l [B,S,D] ----
#pragma unroll
    for (int mt = 0; mt < 2; mt++) {
        float inv0 = 1.f / run_sum[mt][0];
        float inv1 = 1.f / run_sum[mt][1];
        size_t grow0 = (size_t)b * S_ + (q0 + wid * 32 + mt * 16 + qr);
#pragma unroll
        for (int nt = 0; nt < 8; nt++) {
            int col = h * HD_ + nt * 8 + qc2;
            uint32_t lo;
            uint32_t hi = pack_hl(cacc[mt][nt][0] * inv0, cacc[mt][nt][1] * inv0, lo);
            *(uint32_t*)&g_ctx_h[grow0 * D_ + col] = hi;
            *(uint32_t*)&g_ctx_l[grow0 * D_ + col] = lo;
            hi = pack_hl(cacc[mt][nt][2] * inv1, cacc[mt][nt][3] * inv1, lo);
            *(uint32_t*)&g_ctx_h[(grow0 + 8) * D_ + col] = hi;
            *(uint32_t*)&g_ctx_l[(grow0 + 8) * D_ + col] = lo;
        }
    }
}

// ---------------------------------------------------------------------------
extern "C" void kernel_launch(void* const* d_in, const int* in_sizes, int n_in,
                              void* d_out, int out_size)
{
    const float* hidden = (const float*)d_in[0];
    const float* mask   = (const float*)d_in[1];
    const float* at     = (const float*)d_in[2];
    const float* Wq     = (const float*)d_in[3];
    const float* bq     = (const float*)d_in[4];
    const float* Wk     = (const float*)d_in[5];
    const float* bk     = (const float*)d_in[6];
    const float* Wv     = (const float*)d_in[7];
    const float* bv     = (const float*)d_in[8];
    const float* Wo     = (const float*)d_in[9];
    const float* bo     = (const float*)d_in[10];

    float* outp = (float*)d_out;
    const int OUT_ELEMS = 4194304;            // B*S*D
    float* scores = (out_size >= OUT_ELEMS + 1) ? (outp + OUT_ELEMS) : nullptr;

    cudaFuncSetAttribute(gemm_mma, cudaFuncAttributeMaxDynamicSharedMemorySize,
                         GSMEM);
    cudaFuncSetAttribute(attn_mma, cudaFuncAttributeMaxDynamicSharedMemorySize,
                         ASMEM);

    __nv_bfloat16 *hid_h, *hid_l, *ctx_h, *ctx_l, *w_h0, *w_l0;
    cudaGetSymbolAddress((void**)&hid_h, g_hid_h);
    cudaGetSymbolAddress((void**)&hid_l, g_hid_l);
    cudaGetSymbolAddress((void**)&ctx_h, g_ctx_h);
    cudaGetSymbolAddress((void**)&ctx_l, g_ctx_l);
    cudaGetSymbolAddress((void**)&w_h0, g_w_h);
    cudaGetSymbolAddress((void**)&w_l0, g_w_l);

    // 1) split fp32 -> bf16 hi/lo (hidden separate; 4 weights batched)
    const int n4_hid = M_ * D_ / 4;
    const int n4_w   = D_ * D_ / 4;
    split_kernel<<<(n4_hid + 255)/256, 256>>>(hidden, hid_h, hid_l, n4_hid);
    {
        dim3 gs((n4_w + 255)/256, 4);
        split4_kernel<<<gs, 256>>>(Wq, Wk, Wv, Wo, w_h0, w_l0, n4_w);
    }

    // 2) QKV projections — THREE separate launches (exact R10 config)
    dim3 gg(M_/128, D_/128);
    gemm_mma<<<gg, 256, GSMEM>>>(hid_h, hid_l,
                                 w_h0 + 0*(size_t)D_*D_, w_l0 + 0*(size_t)D_*D_,
                                 bq, nullptr, 0);
    gemm_mma<<<gg, 256, GSMEM>>>(hid_h, hid_l,
                                 w_h0 + 1*(size_t)D_*D_, w_l0 + 1*(size_t)D_*D_,
                                 bk, nullptr, 1);
    gemm_mma<<<gg, 256, GSMEM>>>(hid_h, hid_l,
                                 w_h0 + 2*(size_t)D_*D_, w_l0 + 2*(size_t)D_*D_,
                                 bv, nullptr, 2);

    // 3) attention (exact R10 kernel)
    dim3 ga(S_/BQ, B_*NH_);              // 16 x 32
    attn_mma<<<ga, ATHREADS, ASMEM>>>(at, mask, scores);

    // 4) O projection
    gemm_mma<<<gg, 256, GSMEM>>>(ctx_h, ctx_l,
                                 w_h0 + 3*(size_t)D_*D_, w_l0 + 3*(size_t)D_*D_,
                                 bo, outp, 3);
}